// round 16
// baseline (speedup 1.0000x reference)
#include <cuda_runtime.h>
#include <cstdint>

#define TT 512
#define BB_ 64
#define HH 512
#define II 256
#define NG 2048  // 4*H

#define NCTA_REC 128
#define REC_THREADS 256
#define REC_SMEM ((32768 + 8192 + 1024) * 4)  // W(128KB) + h(32KB) + gates(4KB)

// 256 MB scratch for the precomputed input projection (sanctioned __device__ scratch).
__device__ float g_xg[(size_t)TT * BB_ * NG];
// Slot flags: [bblk(4)][pair(4)][jblk(32)] — one 128B line per (bblk,pair).
__device__ unsigned g_flag[512];

static __device__ __forceinline__ unsigned ld_acq_gpu(unsigned* p) {
  unsigned v;
  asm volatile("ld.acquire.gpu.u32 %0, [%1];" : "=r"(v) : "l"(p) : "memory");
  return v;
}

static __device__ __forceinline__ void st_rel_gpu(unsigned* p, unsigned v) {
  asm volatile("st.relaxed.gpu.u32 [%0], %1;" :: "l"(p), "r"(v) : "memory");
}

static __device__ __forceinline__ void bar_sync(int id, int cnt) {
  asm volatile("bar.sync %0, %1;" :: "r"(id), "r"(cnt) : "memory");
}

static __device__ __forceinline__ float fast_sigmoid(float x) {
  return __fdividef(1.0f, 1.0f + __expf(-x));
}
static __device__ __forceinline__ float fast_tanh(float x) {
  float ax = fabsf(x);
  float e = __expf(-2.0f * ax);
  float r = __fdividef(1.0f - e, 1.0f + e);
  return copysignf(r, x);
}

// Packed dual-fp32 FMA: d = a*b + d elementwise on (lo,hi) pairs.
static __device__ __forceinline__ void fma2(unsigned long long& d,
                                            unsigned long long a,
                                            unsigned long long b) {
  asm("fma.rn.f32x2 %0, %1, %2, %0;" : "+l"(d) : "l"(a), "l"(b));
}

static __device__ __forceinline__ float2 unpack2(unsigned long long x) {
  float2 f;
  asm("mov.b64 {%0, %1}, %2;" : "=f"(f.x), "=f"(f.y) : "l"(x));
  return f;
}

static __device__ __forceinline__ unsigned long long dup2(float x) {
  unsigned long long r;
  asm("mov.b64 %0, {%1, %1};" : "=l"(r) : "f"(x));
  return r;
}

// 128-bit shared load straight into two b64 (k,k+1) pairs — no pack movs.
static __device__ __forceinline__ void lds_v2u64(unsigned long long& a,
                                                 unsigned long long& b,
                                                 uint32_t addr) {
  asm("ld.shared.v2.u64 {%0, %1}, [%2];" : "=l"(a), "=l"(b) : "r"(addr));
}

// ---------------------------------------------------------------------------
// Phase 1: xg[t*B+b, n] = sum_k x[t,b,k] * w_ih[n,k] + b_ih[n] + b_hh[n]
// 128x128x16 SGEMM tile, 256 threads, 8x8 micro-tile, FFMA2 inner product.
// Also resets the 512 slot flags (graph-replay determinism).
// ---------------------------------------------------------------------------
__global__ __launch_bounds__(256) void xg_gemm_kernel(
    const float* __restrict__ x, const float* __restrict__ w_ih,
    const float* __restrict__ b_ih, const float* __restrict__ b_hh) {
  if (blockIdx.x == 0 && blockIdx.y == 0) {
    for (int i = threadIdx.x; i < 512; i += 256) g_flag[i] = 0u;
  }

  __shared__ float Asm[16][132];
  __shared__ float Bsm[16][132];

  const int tid = threadIdx.x;
  const int tx = tid & 15;
  const int ty = tid >> 4;
  const int m0 = blockIdx.y * 128;
  const int n0 = blockIdx.x * 128;

  unsigned long long acc2[8][4];  // [m-row][n-pair]
#pragma unroll
  for (int i = 0; i < 8; ++i)
#pragma unroll
    for (int j = 0; j < 4; ++j) acc2[i][j] = 0ull;

  for (int k0 = 0; k0 < II; k0 += 16) {
#pragma unroll
    for (int r = 0; r < 2; ++r) {
      int idx = tid + r * 256;
      int m = idx >> 2;
      int kq = idx & 3;
      float4 v = *reinterpret_cast<const float4*>(
          &x[(size_t)(m0 + m) * II + k0 + kq * 4]);
      Asm[kq * 4 + 0][m] = v.x; Asm[kq * 4 + 1][m] = v.y;
      Asm[kq * 4 + 2][m] = v.z; Asm[kq * 4 + 3][m] = v.w;
      float4 w = *reinterpret_cast<const float4*>(
          &w_ih[(size_t)(n0 + m) * II + k0 + kq * 4]);
      Bsm[kq * 4 + 0][m] = w.x; Bsm[kq * 4 + 1][m] = w.y;
      Bsm[kq * 4 + 2][m] = w.z; Bsm[kq * 4 + 3][m] = w.w;
    }
    __syncthreads();
#pragma unroll
    for (int kk = 0; kk < 16; ++kk) {
      float4 a0 = *reinterpret_cast<const float4*>(&Asm[kk][ty * 4]);
      float4 a1 = *reinterpret_cast<const float4*>(&Asm[kk][64 + ty * 4]);
      ulonglong2 bq0 = *reinterpret_cast<const ulonglong2*>(&Bsm[kk][tx * 4]);
      ulonglong2 bq1 = *reinterpret_cast<const ulonglong2*>(&Bsm[kk][64 + tx * 4]);
      unsigned long long bp[4] = {bq0.x, bq0.y, bq1.x, bq1.y};
      float av[8] = {a0.x, a0.y, a0.z, a0.w, a1.x, a1.y, a1.z, a1.w};
#pragma unroll
      for (int i = 0; i < 8; ++i) {
        unsigned long long aa = dup2(av[i]);
#pragma unroll
        for (int j = 0; j < 4; ++j) fma2(acc2[i][j], aa, bp[j]);
      }
    }
    __syncthreads();
  }

  const float4* bi4 = reinterpret_cast<const float4*>(b_ih);
  const float4* bh4 = reinterpret_cast<const float4*>(b_hh);
  int nb = (n0 >> 2) + tx;
  float4 u0 = bi4[nb], v0 = bh4[nb];
  float4 u1 = bi4[nb + 16], v1 = bh4[nb + 16];
  float4 bias0 = make_float4(u0.x + v0.x, u0.y + v0.y, u0.z + v0.z, u0.w + v0.w);
  float4 bias1 = make_float4(u1.x + v1.x, u1.y + v1.y, u1.z + v1.z, u1.w + v1.w);

#pragma unroll
  for (int hm = 0; hm < 2; ++hm)
#pragma unroll
    for (int i = 0; i < 4; ++i) {
      int m = m0 + hm * 64 + ty * 4 + i;
      int mi = hm * 4 + i;
      float* dst = &g_xg[(size_t)m * NG + n0];
      float2 p0 = unpack2(acc2[mi][0]);
      float2 p1 = unpack2(acc2[mi][1]);
      float2 p2 = unpack2(acc2[mi][2]);
      float2 p3 = unpack2(acc2[mi][3]);
      float4 o0 = make_float4(p0.x + bias0.x, p0.y + bias0.y,
                              p1.x + bias0.z, p1.y + bias0.w);
      float4 o1 = make_float4(p2.x + bias1.x, p2.y + bias1.y,
                              p3.x + bias1.z, p3.y + bias1.w);
      *reinterpret_cast<float4*>(&dst[tx * 4]) = o0;
      *reinterpret_cast<float4*>(&dst[64 + tx * 4]) = o1;
    }
}

// ---------------------------------------------------------------------------
// Phase 2: persistent recurrence — R12 structure (best so far) with two
// latency cuts:
//  (1) slot-flag barrier: 32 per-CTA flag words in one 128B line per
//      (bblk,pair); writer st.relaxed after fence+bar, waiters acquire-poll
//      all 32 flags in one wavefront + __ballot. No contended atomics.
//  (2) split h-copy/dot pipeline: all 8 h LDGs issued up front; k<256 staged
//      then dot m=0..7 runs while k>=256 sits in registers; staged, bar,
//      dot m=8..15. Hides half the h L2 reload under compute.
// Everything else verbatim from R12 (passing, rel_err 2.29e-7).
// ---------------------------------------------------------------------------
__global__ __launch_bounds__(REC_THREADS, 1) void lstm_rec_kernel(
    const float* __restrict__ h0, const float* __restrict__ c0,
    const float* __restrict__ w_hh, float* __restrict__ out) {
  extern __shared__ float sm[];
  float* Wsm = sm;                   // 64 rows x 512 k = 32768 floats
  float* hsm = sm + 32768;           // 16 rows x 512 k = 8192 floats
  float* gsm = sm + 32768 + 8192;    // 256 outputs x 4 gates = 1024 floats

  const int tid = threadIdx.x;
  const int jblk = blockIdx.x & 31;  // 32 j-blocks
  const int bblk = blockIdx.x >> 5;  // 4 b-blocks
  const int j0 = jblk * 16;
  const int b0 = bblk * 16;

  const int pair = tid >> 6;         // 0..3
  const int ptid = tid & 63;         // 0..63 within pair
  unsigned* flags = &g_flag[(bblk * 4 + pair) * 32];
  const int barid = 1 + pair;

  // --- load w_hh slice into smem: Wsm[(jl*4+g)*512 + k] (once) ---
  {
    const float4* w4 = reinterpret_cast<const float4*>(w_hh);
    float4* Wd = reinterpret_cast<float4*>(Wsm);
#pragma unroll
    for (int r = 0; r < 32; ++r) {
      int f4 = tid + r * REC_THREADS;  // 0..8191
      int row = f4 >> 7;               // jl*4+g, 0..63
      int col = f4 & 127;
      int jl = row >> 2, g = row & 3;
      Wd[f4] = w4[(size_t)(g * HH + j0 + jl) * (HH / 4) + col];
    }
  }

  const uint32_t hsm_u32 = (uint32_t)__cvta_generic_to_shared(hsm);
  const uint32_t wsm_u32 = (uint32_t)__cvta_generic_to_shared(Wsm);

  // dot-phase role: tid = tile*8 + ks ; tile = bt*8 + jt ; bt == pair
  const int ks = tid & 7;            // k-split lane (8-way)
  const int tile = tid >> 3;         // 0..31
  const int jt = tile & 7;           // 8 j-tiles of 2 rows (x4 gates)
  const int bt = tile >> 3;          // == pair

  // reduce-scatter ownership (R12 verbatim)
  const int b_own = ((ks & 1) << 2) | (ks & 2) | ((ks >> 2) & 1);

  // activation-phase role: one (b,j) output per thread
  const int jl_o = tid & 15;
  const int bl_o = tid >> 4;
  const int b_o = b0 + bl_o;
  const int j_o = j0 + jl_o;

  float creg = c0[(size_t)b_o * HH + j_o];

  float* hf = out + (size_t)TT * BB_ * HH;
  float* cf = hf + (size_t)BB_ * HH;

  __syncthreads();  // W staged before any pair proceeds

  for (int t = 0; t < TT; ++t) {
    // prefetch this thread's xg gates (overlaps the wait + dot)
    const float* xrow = g_xg + ((size_t)t * BB_ + b_o) * NG + j_o;
    float xg0 = xrow[0];
    float xg1 = xrow[HH];
    float xg2 = xrow[2 * HH];
    float xg3 = xrow[3 * HH];

    // slot-flag wait: each lane acquires one flag; one wavefront per poll
    if (t > 0) {
      const unsigned target = (unsigned)t;
      unsigned* fp = &flags[ptid & 31];
      unsigned v;
      do {
        v = ld_acq_gpu(fp);
      } while (__ballot_sync(0xffffffffu, v < target));
    }

    // ---- h reload, software-pipelined in two k-halves ----
    const float* hbase = (t == 0)
        ? (h0 + (size_t)b0 * HH)
        : (out + (size_t)(t - 1) * BB_ * HH + (size_t)b0 * HH);
    const float4* s4 = reinterpret_cast<const float4*>(hbase) + pair * 512;
    float4* d4 = reinterpret_cast<float4*>(hsm) + pair * 512;

    float4 p1[4], p2[4];
#pragma unroll
    for (int r = 0; r < 4; ++r) p1[r] = s4[r * 128 + ptid];         // k<256
#pragma unroll
    for (int r = 0; r < 4; ++r) p2[r] = s4[r * 128 + 64 + ptid];    // k>=256
#pragma unroll
    for (int r = 0; r < 4; ++r) d4[r * 128 + ptid] = p1[r];
    bar_sync(barid, 64);

    // ---- dot (R12 body), half 1: m = 0..7 (k < 256) ----
    unsigned long long acc[32];  // [i(4 b-rows)][jj(2)][g(4)], k-pair packed
#pragma unroll
    for (int v = 0; v < 32; ++v) acc[v] = 0ull;

    const uint32_t hrow_base = hsm_u32 + (uint32_t)(bt * 4) * HH * 4u;
    const uint32_t wrow_base = wsm_u32 + (uint32_t)(jt * 2) * 4u * HH * 4u;

#pragma unroll 2
    for (int m = 0; m < 8; ++m) {
      const uint32_t kb = (uint32_t)(m * 32 + ks * 4);
      unsigned long long ha[4], hb[4];
#pragma unroll
      for (int i = 0; i < 4; ++i)
        lds_v2u64(ha[i], hb[i], hrow_base + (uint32_t)(i * HH + kb) * 4u);
#pragma unroll
      for (int jj = 0; jj < 2; ++jj)
#pragma unroll
        for (int g = 0; g < 4; ++g) {
          unsigned long long wa, wb;
          lds_v2u64(wa, wb, wrow_base + (uint32_t)((jj * 4 + g) * HH + kb) * 4u);
#pragma unroll
          for (int i = 0; i < 4; ++i) {
            fma2(acc[(i * 2 + jj) * 4 + g], ha[i], wa);
            fma2(acc[(i * 2 + jj) * 4 + g], hb[i], wb);
          }
        }
    }

    // stage half 2 (data already in registers), then finish the dot
#pragma unroll
    for (int r = 0; r < 4; ++r) d4[r * 128 + 64 + ptid] = p2[r];
    bar_sync(barid, 64);

#pragma unroll 2
    for (int m = 8; m < 16; ++m) {
      const uint32_t kb = (uint32_t)(m * 32 + ks * 4);
      unsigned long long ha[4], hb[4];
#pragma unroll
      for (int i = 0; i < 4; ++i)
        lds_v2u64(ha[i], hb[i], hrow_base + (uint32_t)(i * HH + kb) * 4u);
#pragma unroll
      for (int jj = 0; jj < 2; ++jj)
#pragma unroll
        for (int g = 0; g < 4; ++g) {
          unsigned long long wa, wb;
          lds_v2u64(wa, wb, wrow_base + (uint32_t)((jj * 4 + g) * HH + kb) * 4u);
#pragma unroll
          for (int i = 0; i < 4; ++i) {
            fma2(acc[(i * 2 + jj) * 4 + g], ha[i], wa);
            fma2(acc[(i * 2 + jj) * 4 + g], hb[i], wb);
          }
        }
    }

    // collapse k-pairs, 3-level reduce-scatter over 8 ks lanes (R12 verbatim)
    float r[32];
#pragma unroll
    for (int v = 0; v < 32; ++v) {
      float2 f = unpack2(acc[v]);
      r[v] = f.x + f.y;
    }
    {
      const bool u1 = (ks & 1) != 0;
#pragma unroll
      for (int i = 0; i < 16; ++i) {
        float send = u1 ? r[i] : r[i + 16];
        float recv = __shfl_xor_sync(0xffffffffu, send, 1);
        float keep = u1 ? r[i + 16] : r[i];
        r[i] = keep + recv;
      }
      const bool u2 = (ks & 2) != 0;
#pragma unroll
      for (int i = 0; i < 8; ++i) {
        float send = u2 ? r[i] : r[i + 8];
        float recv = __shfl_xor_sync(0xffffffffu, send, 2);
        float keep = u2 ? r[i + 8] : r[i];
        r[i] = keep + recv;
      }
      const bool u3 = (ks & 4) != 0;
#pragma unroll
      for (int i = 0; i < 4; ++i) {
        float send = u3 ? r[i] : r[i + 4];
        float recv = __shfl_xor_sync(0xffffffffu, send, 4);
        float keep = u3 ? r[i + 4] : r[i];
        r[i] = keep + recv;
      }
    }
    {
      const int i_own = b_own >> 1;
      const int jj_own = b_own & 1;
      const int o = (bt * 4 + i_own) * 16 + jt * 2 + jj_own;
      *reinterpret_cast<float4*>(&gsm[o * 4]) =
          make_float4(r[0], r[1], r[2], r[3]);
    }
    bar_sync(barid, 64);

    // ---- act: one output per thread (pair-local region of gsm) ----
    {
      float4 gv = *reinterpret_cast<const float4*>(&gsm[tid * 4]);
      float ig = fast_sigmoid(gv.x + xg0);
      float fg = fast_sigmoid(gv.y + xg1);
      float tg = fast_tanh(gv.z + xg2);
      float og = fast_sigmoid(gv.w + xg3);
      float c = fg * creg + ig * tg;
      creg = c;
      float h = og * fast_tanh(c);

      out[(size_t)t * BB_ * HH + (size_t)b_o * HH + j_o] = h;
      if (t == TT - 1) {
        hf[(size_t)b_o * HH + j_o] = h;
        cf[(size_t)b_o * HH + j_o] = c;
      }
    }

    // release: fence + bar orders all 64 threads' h stores, then slot write
    if (t != TT - 1) {
      __threadfence();
      bar_sync(barid, 64);
      if (ptid == 0) st_rel_gpu(&flags[jblk], (unsigned)(t + 1));
    }
  }
}

extern "C" void kernel_launch(void* const* d_in, const int* in_sizes, int n_in,
                              void* d_out, int out_size) {
  (void)in_sizes; (void)n_in; (void)out_size;
  const float* x    = (const float*)d_in[0];
  const float* h0   = (const float*)d_in[1];
  const float* c0   = (const float*)d_in[2];
  const float* w_ih = (const float*)d_in[3];
  const float* w_hh = (const float*)d_in[4];
  const float* b_ih = (const float*)d_in[5];
  const float* b_hh = (const float*)d_in[6];
  float* out = (float*)d_out;

  cudaFuncSetAttribute(lstm_rec_kernel,
                       cudaFuncAttributeMaxDynamicSharedMemorySize, REC_SMEM);

  // Phase 1: input projection for all timesteps (also resets the slot flags)
  xg_gemm_kernel<<<dim3(NG / 128, (TT * BB_) / 128), 256>>>(x, w_ih, b_ih, b_hh);
  // Phase 2: persistent recurrence (R12 + slot flags + pipelined h reload)
  lstm_rec_kernel<<<NCTA_REC, REC_THREADS, REC_SMEM>>>(h0, c0, w_hh, out);
}